// round 16
// baseline (speedup 1.0000x reference)
#include <cuda_runtime.h>
#include <cuda_bf16.h>
#include <cstdint>
#include <cstddef>

#define BDIM 64
#define CIN  256
#define CO1  256
#define HWP  1024
#define LF2  1024

// ---------------- scratch (device globals; no allocation) ----------------
__device__ float g_kT[(size_t)BDIM * HWP * LF2];     // conv2 output, [b][n][oc] fp32
__device__ float g_w2beta[LF2];
__device__ float g_a1[CO1], g_d1[CO1];
__device__ float g_a2[LF2], g_d2[LF2];
__device__ float g_p1s[1024 * 256],  g_p1ss[1024 * 256];   // conv1-fused BN1 partials
__device__ float g_p2s[512 * 1024],  g_p2ss[512 * 1024];   // conv2-fused BN2 partials
// conv1 weights: packed 2-tap stage tiles, K=16 chunks, taps padded 49->50.
// stage_id = (kc16*25 + tp)*2 + coHalf ; stage tile = 2 taps x (128 co x 80B).
// Pad tap 49 tiles are never written -> stay zero (device globals zero-init).
__device__ __align__(128) char g_wpk[16 * 25 * 2 * 20480];
// conv1 x operand: [b][uv][ci] bf16 hi/mid
__device__ __align__(16) __nv_bfloat16 g_xhi [(size_t)BDIM * HWP * CIN];
__device__ __align__(16) __nv_bfloat16 g_xmid[(size_t)BDIM * HWP * CIN];
// out-GEMM B operand: x split, original layout [b][ci][uv]
__device__ __align__(16) __nv_bfloat16 g_xchi [(size_t)BDIM * CIN * HWP];
__device__ __align__(16) __nv_bfloat16 g_xcmid[(size_t)BDIM * CIN * HWP];
// conv1 output transposed split: [b][px][c]
__device__ __align__(16) __nv_bfloat16 g_hThi [(size_t)BDIM * HWP * CIN];
__device__ __align__(16) __nv_bfloat16 g_hTmid[(size_t)BDIM * HWP * CIN];
// conv2 folded weights split: [oc][c]
__device__ __align__(16) __nv_bfloat16 g_w2fhi [LF2 * CIN];
__device__ __align__(16) __nv_bfloat16 g_w2fmid[LF2 * CIN];
// softmax output transposed split: [b][n][uv]
__device__ __align__(16) __nv_bfloat16 g_sThi [(size_t)BDIM * HWP * LF2];
__device__ __align__(16) __nv_bfloat16 g_sTmid[(size_t)BDIM * HWP * LF2];

// ---------------- family-common PTX helpers ----------------
__device__ __forceinline__ uint32_t smem_u32(const void* p) {
    uint32_t a;
    asm("{ .reg .u64 t; cvta.to.shared.u64 t, %1; cvt.u32.u64 %0, t; }" : "=r"(a) : "l"(p));
    return a;
}
__device__ __forceinline__ void cp_async16(uint32_t dst, const void* src, uint32_t srcsize) {
    asm volatile("cp.async.cg.shared.global [%0], [%1], 16, %2;"
                 :: "r"(dst), "l"(src), "r"(srcsize));
}
__device__ __forceinline__ void cp_commit() {
    asm volatile("cp.async.commit_group;");
}
template <int N> __device__ __forceinline__ void cp_wait() {
    asm volatile("cp.async.wait_group %0;" :: "n"(N));
}
// 1D bulk copy gmem->smem, mbarrier-completed (async engine, bypasses LSU)
__device__ __forceinline__ void cp_bulk_g2s(uint32_t dst, const void* src,
                                            uint32_t bytes, uint32_t mbar) {
    asm volatile(
        "cp.async.bulk.shared::cluster.global.mbarrier::complete_tx::bytes [%0], [%1], %2, [%3];"
        :: "r"(dst), "l"(src), "r"(bytes), "r"(mbar) : "memory");
}
#define MBARRIER_INIT(addr, count) \
    asm volatile("mbarrier.init.shared.b64 [%0], %1;" \
        :: "r"((uint32_t)(addr)), "r"((uint32_t)(count)) : "memory")
#define MBARRIER_EXPECT_TX(addr, bytes) \
    asm volatile("mbarrier.arrive.expect_tx.shared.b64 _, [%0], %1;" \
        :: "r"((uint32_t)(addr)), "r"((uint32_t)(bytes)) : "memory")
#define MBARRIER_WAIT_PARITY(mbar_smem_addr, phase_parity) do { \
    uint32_t _mbar = (uint32_t)(mbar_smem_addr); \
    uint32_t _parity = (uint32_t)(phase_parity); \
    uint32_t _done; \
    asm volatile("{ .reg .pred p; mbarrier.try_wait.parity.acquire.cta.shared::cta.b64 p, [%1], %2; selp.b32 %0, 1, 0, p; }" \
        : "=r"(_done) : "r"(_mbar), "r"(_parity) : "memory"); \
    if (!_done) { \
        asm volatile("{ .reg .pred P1; WAIT_LOOP_%=: mbarrier.try_wait.parity.acquire.cta.shared::cta.b64 P1, [%0], %1, 0x989680; @P1 bra.uni WAIT_DONE_%=; bra.uni WAIT_LOOP_%=; WAIT_DONE_%=: }" \
            :: "r"(_mbar), "r"(_parity) : "memory"); \
    } \
} while (0)

__device__ __forceinline__ void ldsm4(uint32_t* r, uint32_t addr) {
    asm volatile("ldmatrix.sync.aligned.m8n8.x4.shared.b16 {%0,%1,%2,%3}, [%4];"
                 : "=r"(r[0]), "=r"(r[1]), "=r"(r[2]), "=r"(r[3]) : "r"(addr));
}
__device__ __forceinline__ void mma_bf16(float* c, const uint32_t* a, const uint32_t* b) {
    asm volatile(
        "mma.sync.aligned.m16n8k16.row.col.f32.bf16.bf16.f32 "
        "{%0,%1,%2,%3}, {%4,%5,%6,%7}, {%8,%9}, {%0,%1,%2,%3};"
        : "+f"(c[0]), "+f"(c[1]), "+f"(c[2]), "+f"(c[3])
        : "r"(a[0]), "r"(a[1]), "r"(a[2]), "r"(a[3]), "r"(b[0]), "r"(b[1]));
}

// FMA-pipe exp (avoids MUFU throughput wall): 2^t with deg-6 Taylor on frac,
// abs err <= ~2.5e-5 over [0,1). Inputs are BN-standardized logits (|v| small).
__device__ __forceinline__ float fast_exp(float v) {
    float t = v * 1.4426950408889634f;
    t = fminf(fmaxf(t, -120.f), 120.f);
    float fi = floorf(t);
    float f = t - fi;
    float p = 1.5403530393381608e-4f;
    p = fmaf(p, f, 1.3333558146428443e-3f);
    p = fmaf(p, f, 9.618129107628477e-3f);
    p = fmaf(p, f, 5.550410866482158e-2f);
    p = fmaf(p, f, 2.402265069591007e-1f);
    p = fmaf(p, f, 6.931471805599453e-1f);
    p = fmaf(p, f, 1.0f);
    float sc = __int_as_float(((int)fi + 127) << 23);
    return p * sc;
}

// ---------------- profiling pad (keeps conv1 at ncu's launch index 3) ----------------
__global__ void prof_pad_kernel() {}

// ---------------- prep: w1 -> packed 2-tap K16 stage tiles ----------------
__global__ void split_w1_kernel(const float* __restrict__ w1) {
    int i = blockIdx.x * 256 + threadIdx.x;
    if (i >= 49 * 256 * 256) return;
    int ci = i & 255, co = (i >> 8) & 255, tap = i >> 16;
    float v = w1[(co * 256 + ci) * 49 + tap];
    __nv_bfloat16 hi = __float2bfloat16(v);
    __nv_bfloat16 mid = __float2bfloat16(v - __bfloat162float(hi));
    int kc = ci >> 4, ciw = ci & 15;
    int stage = (kc * 25 + (tap >> 1)) * 2 + (co >> 7);
    char* tb = g_wpk + (size_t)stage * 20480 + (tap & 1) * 10240 + (co & 127) * 80;
    *(__nv_bfloat16*)(tb + ciw * 2)      = hi;   // bytes [0,32)
    *(__nv_bfloat16*)(tb + 32 + ciw * 2) = mid;  // bytes [32,64); [64,80) pad
}

// ---------------- prep: split x -> transposed [b][uv][ci] AND original [b][ci][uv] ----------------
__global__ void split_x_kernel(const float* __restrict__ x) {
    __shared__ float t[32][33];
    int b   = blockIdx.z;
    int uv0 = blockIdx.x << 5;
    int ci0 = blockIdx.y << 5;
    int tx = threadIdx.x, ty = threadIdx.y;   // (32, 8)
#pragma unroll
    for (int r = 0; r < 4; r++) {
        int ci = ci0 + ty + r * 8;
        float v = x[((size_t)(b * 256 + ci) << 10) + uv0 + tx];
        t[ty + r * 8][tx] = v;
        __nv_bfloat16 hi = __float2bfloat16(v);
        size_t o = ((size_t)(b * 256 + ci) << 10) + uv0 + tx;
        g_xchi[o]  = hi;
        g_xcmid[o] = __float2bfloat16(v - __bfloat162float(hi));
    }
    __syncthreads();
#pragma unroll
    for (int r = 0; r < 4; r++) {
        int uv = uv0 + ty + r * 8;
        float v = t[tx][ty + r * 8];
        __nv_bfloat16 hi = __float2bfloat16(v);
        size_t o = ((size_t)b << 18) + ((size_t)uv << 8) + ci0 + tx;
        g_xhi[o]  = hi;
        g_xmid[o] = __float2bfloat16(v - __bfloat162float(hi));
    }
}

// ---------------- conv1: K16 halo reuse + 2-tap bulk A stages + 2 CTAs/SM ----------------
// 16 kc16 chunks; per chunk load 704-px halo (hi/mid, 48B rows) once, run 25 2-tap stages.
#define C1_AT     20480
#define C1_RROW   48
#define C1_REG    (704 * C1_RROW)            // 33792
#define C1_A0     1024
#define C1_RH     (1024 + 2 * C1_AT)         // 41984
#define C1_RM     (C1_RH + C1_REG)           // 75776
#define C1_SMEM   (C1_RM + C1_REG)           // 109568

__device__ __forceinline__ void conv1_issue_A(uint32_t sb, int coh, int s) {
    int stage = s * 2 + coh;
    uint32_t mbar = sb + (uint32_t)(s & 1) * 8;
    MBARRIER_EXPECT_TX(mbar, 20480u);
    cp_bulk_g2s(sb + C1_A0 + (uint32_t)(s & 1) * C1_AT,
                g_wpk + (size_t)stage * 20480, 20480u, mbar);
}

__global__ __launch_bounds__(256, 2) void conv1_mma_kernel(const float* __restrict__ b1) {
    extern __shared__ char smem[];
    const uint32_t sb = smem_u32(smem);
    const int tid  = threadIdx.x;
    const int lane = tid & 31;
    const int wid  = tid >> 5;
    const int wm   = wid >> 1;          // 0..3: 32 co each
    const int wn   = wid & 1;           // 0..1: 64 px each
    const int bt   = blockIdx.x;
    const int b    = bt >> 3;
    const int i0   = (bt & 7) << 2;
    const int coh  = blockIdx.y;        // co half 0/1
    const int co0  = coh << 7;

    if (tid == 0) { MBARRIER_INIT(sb, 1); MBARRIER_INIT(sb + 8, 1); }
    __syncthreads();

    float acc[2][8][4];
#pragma unroll
    for (int mf = 0; mf < 2; mf++)
#pragma unroll
        for (int nf = 0; nf < 8; nf++)
#pragma unroll
            for (int e = 0; e < 4; e++) acc[mf][nf][e] = 0.f;

    const uint32_t aRow = (uint32_t)((wm * 32 + (lane & 15)) * 80 + (lane >> 4) * 16);

    if (tid == 0) conv1_issue_A(sb, coh, 0);

    int s = 0;
    for (int kc = 0; kc < 16; kc++) {
        // ---- load halo region for this kc16: (u,v), u in [i0-6,i0+10), v in [-6,38) ----
        {
            const __nv_bfloat16* xh = g_xhi  + ((size_t)b << 18) + (kc << 4);
            const __nv_bfloat16* xm = g_xmid + ((size_t)b << 18) + (kc << 4);
#pragma unroll
            for (int l = 0; l < 11; l++) {
                int idx = l * 256 + tid;              // 0..2815
                int px = idx >> 2;                    // 0..703
                int sel = idx & 3;
                int c16 = sel & 1;                    // 16B chunk within 32B
                int arr = sel >> 1;                   // 0=hi, 1=mid
                int ur = px / 44, vr = px - ur * 44;
                int u = i0 - 6 + ur;
                int v = vr - 6;
                bool in = ((unsigned)u < 32u) && ((unsigned)v < 32u);
                int pix = in ? (u * 32 + v) : 0;
                uint32_t sz = in ? 16u : 0u;
                uint32_t off = (uint32_t)(px * C1_RROW + c16 * 16);
                const __nv_bfloat16* src = (arr ? xm : xh) + ((size_t)pix << 8) + c16 * 8;
                cp_async16(sb + (arr ? C1_RM : C1_RH) + off, src, sz);
            }
            cp_commit();
            cp_wait<0>();
            __syncthreads();
        }
        // ---- 25 stages x 2 taps against the resident region ----
        for (int tp = 0; tp < 25; tp++, s++) {
            const int buf = s & 1;
            MBARRIER_WAIT_PARITY(sb + buf * 8, (s >> 1) & 1);   // A stage s landed
            __syncthreads();   // all warps done with stage s-1 -> its A buffer reusable
            if (tid == 0 && s + 1 < 400) conv1_issue_A(sb, coh, s + 1);

            const uint32_t aT = sb + C1_A0 + (uint32_t)buf * C1_AT;
#pragma unroll
            for (int j = 0; j < 2; j++) {
                int tap = tp * 2 + j;
                int btap = (tap > 48) ? 48 : tap;   // pad tap: zero A tile, clamped B addr
                const int dp = (btap / 7) * 2 - 6;
                const int dq = (btap % 7) * 2 - 6;
                uint32_t ah[2][4], am[2][4];
#pragma unroll
                for (int mf = 0; mf < 2; mf++) {
                    uint32_t addr = aT + (uint32_t)(j * 10240) + aRow + (uint32_t)(mf * 16 * 80);
                    ldsm4(ah[mf], addr);
                    ldsm4(am[mf], addr + 32);
                }
#pragma unroll
                for (int nf2 = 0; nf2 < 4; nf2++) {
                    int n0 = wn * 64 + nf2 * 16;
                    uint32_t pb = (uint32_t)((((n0 >> 5) + dp + 6) * 44 + (n0 & 31) + dq + 6
                                              + (lane & 15)) * C1_RROW + (lane >> 4) * 16);
                    uint32_t r[4];
                    uint32_t bh[2][2], bm[2][2];
                    ldsm4(r, sb + C1_RH + pb);
                    bh[0][0] = r[0]; bh[0][1] = r[2];
                    bh[1][0] = r[1]; bh[1][1] = r[3];
                    ldsm4(r, sb + C1_RM + pb);
                    bm[0][0] = r[0]; bm[0][1] = r[2];
                    bm[1][0] = r[1]; bm[1][1] = r[3];
#pragma unroll
                    for (int mf = 0; mf < 2; mf++)
#pragma unroll
                        for (int jj = 0; jj < 2; jj++) {
                            mma_bf16(acc[mf][nf2 * 2 + jj], ah[mf], bh[jj]);
                            mma_bf16(acc[mf][nf2 * 2 + jj], ah[mf], bm[jj]);
                            mma_bf16(acc[mf][nf2 * 2 + jj], am[mf], bh[jj]);
                        }
                }
            }
        }
        __syncthreads();   // all warps done with region before kc+1 reload
    }

    // epilogue: +bias, split bf16 hi/mid, smem-transpose to [px][co], write g_hT
    __nv_bfloat16* hs = (__nv_bfloat16*)smem;            // [128 px][136]
    __nv_bfloat16* ms = hs + 128 * 136;
#pragma unroll
    for (int mf = 0; mf < 2; mf++) {
        int R = wm * 32 + mf * 16 + (lane >> 2);
        float bias0 = b1[co0 + R];
        float bias8 = b1[co0 + R + 8];
#pragma unroll
        for (int nf = 0; nf < 8; nf++) {
            int C = wn * 64 + nf * 8 + (lane & 3) * 2;
#pragma unroll
            for (int e = 0; e < 4; e++) {
                float v = acc[mf][nf][e] + ((e & 2) ? bias8 : bias0);
                int px = C + (e & 1);
                int co = R + ((e & 2) ? 8 : 0);
                __nv_bfloat16 hi = __float2bfloat16(v);
                hs[px * 136 + co] = hi;
                ms[px * 136 + co] = __float2bfloat16(v - __bfloat162float(hi));
            }
        }
    }
    __syncthreads();
    {
        int px = tid >> 1;
        int half = tid & 1;
        size_t dst = (((size_t)b * HWP + i0 * 32 + px) << 8) + co0 + half * 64;
        const uint4* srcH = (const uint4*)(hs + px * 136 + half * 64);
        const uint4* srcM = (const uint4*)(ms + px * 136 + half * 64);
        uint4* dH = (uint4*)(g_hThi  + dst);
        uint4* dM = (uint4*)(g_hTmid + dst);
#pragma unroll
        for (int q = 0; q < 8; q++) { dH[q] = srcH[q]; dM[q] = srcM[q]; }
    }
    // fused BN1 partial stats: per-co sum/ssq over this CTA's 128 px
    {
        int co = tid & 127, half = tid >> 7;
        float s2 = 0.f, ss = 0.f;
#pragma unroll 8
        for (int p = 0; p < 64; p++) {
            int px = half * 64 + p;
            float v = __bfloat162float(hs[px * 136 + co]) + __bfloat162float(ms[px * 136 + co]);
            s2 += v; ss += v * v;
        }
        int prow = bt * 2 + half;
        g_p1s [prow * 256 + co0 + co] = s2;
        g_p1ss[prow * 256 + co0 + co] = ss;
    }
}

// ---------------- BN1 final: reduce 1024 partial rows -> a,d ----------------
__global__ void bn1_final_kernel(const float* __restrict__ gamma,
                                 const float* __restrict__ beta) {
    int c = blockIdx.x, t = threadIdx.x;
    __shared__ float sh[256], sh2[256];
    sh[t]  = g_p1s [t * 256 + c] + g_p1s [(t + 256) * 256 + c]
           + g_p1s [(t + 512) * 256 + c] + g_p1s [(t + 768) * 256 + c];
    sh2[t] = g_p1ss[t * 256 + c] + g_p1ss[(t + 256) * 256 + c]
           + g_p1ss[(t + 512) * 256 + c] + g_p1ss[(t + 768) * 256 + c];
    __syncthreads();
    for (int st = 128; st > 0; st >>= 1) {
        if (t < st) { sh[t] += sh[t + st]; sh2[t] += sh2[t + st]; }
        __syncthreads();
    }
    if (t == 0) {
        float mean = sh[0] * (1.f / 65536.f);
        float var  = sh2[0] * (1.f / 65536.f) - mean * mean;
        float a = gamma[c] * rsqrtf(var + 1e-5f);
        g_a1[c] = a;
        g_d1[c] = beta[c] - mean * a;
    }
}

// ---------------- fold BN1 into conv2 weights, split bf16 ----------------
__global__ void fold2_kernel(const float* __restrict__ w2, const float* __restrict__ b2) {
    int oc = blockIdx.x;
    int c  = threadIdx.x;
    float wv = w2[oc * CIN + c];
    float wf = wv * g_a1[c];
    __nv_bfloat16 hi = __float2bfloat16(wf);
    g_w2fhi[oc * 256 + c]  = hi;
    g_w2fmid[oc * 256 + c] = __float2bfloat16(wf - __bfloat162float(hi));
    __shared__ float sh[256];
    sh[c] = wv * g_d1[c];
    __syncthreads();
    for (int st = 128; st > 0; st >>= 1) {
        if (c < st) sh[c] += sh[c + st];
        __syncthreads();
    }
    if (c == 0) g_w2beta[oc] = b2[oc] + sh[0];
}

// ---------------- shared GEMM geometry for conv2 / out (128 M x 256 N tiles) ----------------
#define T_A     18432              // 128 * 144
#define T_B     36864              // 256 * 144
#define G_STAGE (2 * T_A + 2 * T_B)  // 110592
#define G_SMEM  (2 * G_STAGE)        // 221184

// ---------------- conv2: A = w2f [oc][c], B = hT [b][px][c]; C -> g_kT [b][n][oc] ----------------
__device__ __forceinline__ void c2_issue(uint32_t base, int b, int px0, int oc0, int kc, int tid) {
    const __nv_bfloat16* Ah = g_w2fhi  + (size_t)oc0 * 256 + kc * 64;
    const __nv_bfloat16* Am = g_w2fmid + (size_t)oc0 * 256 + kc * 64;
    const __nv_bfloat16* Bh = g_hThi  + (((size_t)b * HWP + px0) << 8) + kc * 64;
    const __nv_bfloat16* Bm = g_hTmid + (((size_t)b * HWP + px0) << 8) + kc * 64;
#pragma unroll
    for (int l = 0; l < 4; l++) {
        int idx = l * 256 + tid;
        int row = idx >> 3, c16 = idx & 7;
        uint32_t off = (uint32_t)(row * 144 + c16 * 16);
        cp_async16(base + off,       Ah + row * 256 + c16 * 8, 16);
        cp_async16(base + T_A + off, Am + row * 256 + c16 * 8, 16);
    }
#pragma unroll
    for (int l = 0; l < 8; l++) {
        int idx = l * 256 + tid;
        int row = idx >> 3, c16 = idx & 7;
        uint32_t off = (uint32_t)(row * 144 + c16 * 16);
        cp_async16(base + 2 * T_A + off,       Bh + (size_t)row * 256 + c16 * 8, 16);
        cp_async16(base + 2 * T_A + T_B + off, Bm + (size_t)row * 256 + c16 * 8, 16);
    }
}

__global__ __launch_bounds__(256, 1) void conv2_mma_kernel() {
    extern __shared__ char smem[];
    const uint32_t sb = smem_u32(smem);
    const int tid = threadIdx.x, lane = tid & 31, wid = tid >> 5;
    const int wm = wid >> 1, wn = wid & 1;
    const int bx = blockIdx.x;
    const int b = bx >> 2, px0 = (bx & 3) << 8;
    const int oc0 = blockIdx.y << 7;

    float acc[2][16][4];
#pragma unroll
    for (int mf = 0; mf < 2; mf++)
#pragma unroll
        for (int nf = 0; nf < 16; nf++)
#pragma unroll
            for (int e = 0; e < 4; e++) acc[mf][nf][e] = 0.f;

    const uint32_t a_rowoff = (uint32_t)((wm * 32 + (lane & 15)) * 144 + (lane >> 4) * 16);
    const uint32_t b_rowoff = (uint32_t)((wn * 128 + (lane & 15)) * 144 + (lane >> 4) * 16);

    c2_issue(sb, b, px0, oc0, 0, tid);
    cp_commit();
    for (int it = 0; it < 4; it++) {
        if (it < 3) {
            c2_issue(sb + (uint32_t)(((it + 1) & 1) * G_STAGE), b, px0, oc0, it + 1, tid);
            cp_commit();
            cp_wait<1>();
        } else {
            cp_wait<0>();
        }
        __syncthreads();
        const uint32_t cur = sb + (uint32_t)((it & 1) * G_STAGE);
#pragma unroll
        for (int ks = 0; ks < 4; ks++) {
            const uint32_t koff = (uint32_t)(ks * 32);
            uint32_t ah[2][4], am[2][4];
#pragma unroll
            for (int mf = 0; mf < 2; mf++) {
                uint32_t addr = cur + a_rowoff + (uint32_t)(mf * 16 * 144) + koff;
                ldsm4(ah[mf], addr);
                ldsm4(am[mf], addr + T_A);
            }
#pragma unroll
            for (int h = 0; h < 2; h++) {
                uint32_t bh[8][2], bm[8][2];
#pragma unroll
                for (int j = 0; j < 4; j++) {
                    uint32_t r[4];
                    uint32_t addr = cur + 2 * T_A + b_rowoff + (uint32_t)((h * 4 + j) * 16 * 144) + koff;
                    ldsm4(r, addr);
                    bh[j * 2][0] = r[0]; bh[j * 2][1] = r[2];
                    bh[j * 2 + 1][0] = r[1]; bh[j * 2 + 1][1] = r[3];
                    ldsm4(r, addr + T_B);
                    bm[j * 2][0] = r[0]; bm[j * 2][1] = r[2];
                    bm[j * 2 + 1][0] = r[1]; bm[j * 2 + 1][1] = r[3];
                }
#pragma unroll
                for (int mf = 0; mf < 2; mf++)
#pragma unroll
                    for (int nf = 0; nf < 8; nf++) {
                        mma_bf16(acc[mf][h * 8 + nf], ah[mf], bh[nf]);
                        mma_bf16(acc[mf][h * 8 + nf], ah[mf], bm[nf]);
                        mma_bf16(acc[mf][h * 8 + nf], am[mf], bh[nf]);
                    }
            }
        }
        __syncthreads();
    }

    // epilogue: +beta2, smem transpose to [px 256][oc 128], write g_kT rows
    float* ts = (float*)smem;    // [256][132]
#pragma unroll
    for (int mf = 0; mf < 2; mf++) {
        int R = wm * 32 + mf * 16 + (lane >> 2);
        float be0 = g_w2beta[oc0 + R];
        float be8 = g_w2beta[oc0 + R + 8];
#pragma unroll
        for (int nf = 0; nf < 16; nf++) {
            int C = wn * 128 + nf * 8 + (lane & 3) * 2;
#pragma unroll
            for (int e = 0; e < 4; e++) {
                int px = C + (e & 1);
                int co = R + ((e & 2) ? 8 : 0);
                ts[px * 132 + co] = acc[mf][nf][e] + ((e & 2) ? be8 : be0);
            }
        }
    }
    __syncthreads();
    {
        int px = tid;
        const uint4* src = (const uint4*)(ts + px * 132);
        uint4* dst = (uint4*)(g_kT + (((size_t)b * HWP + px0 + px) << 10) + oc0);
#pragma unroll
        for (int q = 0; q < 32; q++) dst[q] = src[q];
    }
    // fused BN2 partial stats: per-oc sum/ssq over this CTA's 256 px
    {
        int oc = tid & 127, half = tid >> 7;
        float s = 0.f, ss = 0.f;
#pragma unroll 8
        for (int p = 0; p < 128; p++) {
            float v = ts[(half * 128 + p) * 132 + oc];
            s += v; ss += v * v;
        }
        int prow = bx * 2 + half;
        g_p2s [prow * 1024 + oc0 + oc] = s;
        g_p2ss[prow * 1024 + oc0 + oc] = ss;
    }
}

// ---------------- BN2 final: reduce 512 partial rows -> a,d ----------------
__global__ void bn2_final_kernel(const float* __restrict__ gamma,
                                 const float* __restrict__ beta) {
    int c = blockIdx.x, t = threadIdx.x;
    __shared__ float sh[256], sh2[256];
    sh[t]  = g_p2s [t * 1024 + c] + g_p2s [(t + 256) * 1024 + c];
    sh2[t] = g_p2ss[t * 1024 + c] + g_p2ss[(t + 256) * 1024 + c];
    __syncthreads();
    for (int st = 128; st > 0; st >>= 1) {
        if (t < st) { sh[t] += sh[t + st]; sh2[t] += sh2[t + st]; }
        __syncthreads();
    }
    if (t == 0) {
        float mean = sh[0] * (1.f / 65536.f);
        float var  = sh2[0] * (1.f / 65536.f) - mean * mean;
        float a = gamma[c] * rsqrtf(var + 1e-5f);
        g_a2[c] = a;
        g_d2[c] = beta[c] - mean * a;
    }
}

// ---------------- BN2 + softmax: warp-per-row, FMA-pipe exp ----------------
__global__ __launch_bounds__(256) void softmax_rows_kernel() {
    __shared__ float sa[LF2], sd[LF2];
    int tid = threadIdx.x;
    for (int i = tid; i < LF2; i += 256) { sa[i] = g_a2[i]; sd[i] = g_d2[i]; }
    __syncthreads();
    int wid = tid >> 5, lane = tid & 31;
    size_t r = (size_t)blockIdx.x * 8 + wid;
    const float* src = g_kT + (r << 10);
    float e[32];
    float s = 0.f;
#pragma unroll
    for (int k = 0; k < 32; k++) {
        int oc = lane + k * 32;
        float v = src[oc] * sa[oc] + sd[oc];
        e[k] = fast_exp(v);
        s += e[k];
    }
#pragma unroll
    for (int o = 16; o > 0; o >>= 1) s += __shfl_xor_sync(0xffffffffu, s, o);
    float inv = 1.f / s;
    __nv_bfloat16* dh = g_sThi  + (r << 10);
    __nv_bfloat16* dm = g_sTmid + (r << 10);
#pragma unroll
    for (int k = 0; k < 32; k++) {
        int oc = lane + k * 32;
        float p = e[k] * inv;
        __nv_bfloat16 hi = __float2bfloat16(p);
        dh[oc] = hi;
        dm[oc] = __float2bfloat16(p - __bfloat162float(hi));
    }
}

// ---------------- out GEMM: A = S^T [b][n][uv], B = x [b][c][uv]; C -> out[b][n][c] ----------------
__device__ __forceinline__ void out_issue(uint32_t base, int b, int n0, int kc, int tid) {
    const __nv_bfloat16* Ah = g_sThi  + (((size_t)b * HWP + n0) << 10) + kc * 64;
    const __nv_bfloat16* Am = g_sTmid + (((size_t)b * HWP + n0) << 10) + kc * 64;
    const __nv_bfloat16* Bh = g_xchi  + (((size_t)b * CIN) << 10) + kc * 64;
    const __nv_bfloat16* Bm = g_xcmid + (((size_t)b * CIN) << 10) + kc * 64;
#pragma unroll
    for (int l = 0; l < 4; l++) {
        int idx = l * 256 + tid;
        int row = idx >> 3, c16 = idx & 7;
        uint32_t off = (uint32_t)(row * 144 + c16 * 16);
        cp_async16(base + off,       Ah + ((size_t)row << 10) + c16 * 8, 16);
        cp_async16(base + T_A + off, Am + ((size_t)row << 10) + c16 * 8, 16);
    }
#pragma unroll
    for (int l = 0; l < 8; l++) {
        int idx = l * 256 + tid;
        int row = idx >> 3, c16 = idx & 7;
        uint32_t off = (uint32_t)(row * 144 + c16 * 16);
        cp_async16(base + 2 * T_A + off,       Bh + ((size_t)row << 10) + c16 * 8, 16);
        cp_async16(base + 2 * T_A + T_B + off, Bm + ((size_t)row << 10) + c16 * 8, 16);
    }
}

__global__ __launch_bounds__(256, 1) void out_mma_kernel(float* __restrict__ out) {
    extern __shared__ char smem[];
    const uint32_t sb = smem_u32(smem);
    const int tid = threadIdx.x, lane = tid & 31, wid = tid >> 5;
    const int wm = wid >> 1, wn = wid & 1;
    const int bx = blockIdx.x;
    const int b = bx >> 3, n0 = (bx & 7) << 7;

    float acc[2][16][4];
#pragma unroll
    for (int mf = 0; mf < 2; mf++)
#pragma unroll
        for (int nf = 0; nf < 16; nf++)
#pragma unroll
            for (int e = 0; e < 4; e++) acc[mf][nf][e] = 0.f;

    const uint32_t a_rowoff = (uint32_t)((wm * 32 + (lane & 15)) * 144 + (lane >> 4) * 16);
    const uint32_t b_rowoff = (uint32_t)((wn * 128 + (lane & 15)) * 144 + (lane >> 4) * 16);

    out_issue(sb, b, n0, 0, tid);
    cp_commit();
    for (int it = 0; it < 16; it++) {
        if (it < 15) {
            out_issue(sb + (uint32_t)(((it + 1) & 1) * G_STAGE), b, n0, it + 1, tid);
            cp_commit();
            cp_wait<1>();
        } else {
            cp_wait<0>();
        }
        __syncthreads();
        const uint32_t cur = sb + (uint32_t)((it & 1) * G_STAGE);
#pragma unroll
        for (int ks = 0; ks < 4; ks++) {
            const uint32_t koff = (uint32_t)(ks * 32);
            uint32_t ah[2][4], am[2][4];
#pragma unroll
            for (int mf = 0; mf < 2; mf++) {
                uint32_t addr = cur + a_rowoff + (uint32_t)(mf * 16 * 144) + koff;
                ldsm4(ah[mf], addr);
                ldsm4(am[mf], addr + T_A);
            }
#pragma unroll
            for (int h = 0; h < 2; h++) {
                uint32_t bh[8][2], bm[8][2];
#pragma unroll
                for (int j = 0; j < 4; j++) {
                    uint32_t r[4];
                    uint32_t addr = cur + 2 * T_A + b_rowoff + (uint32_t)((h * 4 + j) * 16 * 144) + koff;
                    ldsm4(r, addr);
                    bh[j * 2][0] = r[0]; bh[j * 2][1] = r[2];
                    bh[j * 2 + 1][0] = r[1]; bh[j * 2 + 1][1] = r[3];
                    ldsm4(r, addr + T_B);
                    bm[j * 2][0] = r[0]; bm[j * 2][1] = r[2];
                    bm[j * 2 + 1][0] = r[1]; bm[j * 2 + 1][1] = r[3];
                }
#pragma unroll
                for (int mf = 0; mf < 2; mf++)
#pragma unroll
                    for (int nf = 0; nf < 8; nf++) {
                        mma_bf16(acc[mf][h * 8 + nf], ah[mf], bh[nf]);
                        mma_bf16(acc[mf][h * 8 + nf], ah[mf], bm[nf]);
                        mma_bf16(acc[mf][h * 8 + nf], am[mf], bh[nf]);
                    }
            }
        }
        __syncthreads();
    }

    // epilogue: direct coalesced float2 stores to out[b][n][c]
#pragma unroll
    for (int mf = 0; mf < 2; mf++) {
        int n = n0 + wm * 32 + mf * 16 + (lane >> 2);
        float* row0 = out + ((size_t)b << 18) + (size_t)n * 256;
        float* row8 = row0 + 8 * 256;
#pragma unroll
        for (int nf = 0; nf < 16; nf++) {
            int C = wn * 128 + nf * 8 + (lane & 3) * 2;
            *(float2*)(row0 + C) = make_float2(acc[mf][nf][0], acc[mf][nf][1]);
            *(float2*)(row8 + C) = make_float2(acc[mf][nf][2], acc[mf][nf][3]);
        }
    }
}

// ---------------- launch ----------------
extern "C" void kernel_launch(void* const* d_in, const int* in_sizes, int n_in,
                              void* d_out, int out_size) {
    const float* x   = (const float*)d_in[0];
    const float* w1  = (const float*)d_in[1];
    const float* b1  = (const float*)d_in[2];
    const float* g1  = (const float*)d_in[3];
    const float* bb1 = (const float*)d_in[4];
    const float* w2  = (const float*)d_in[5];
    const float* b2  = (const float*)d_in[6];
    const float* g2  = (const float*)d_in[7];
    const float* bb2 = (const float*)d_in[8];
    float* out = (float*)d_out;

    cudaFuncSetAttribute(conv1_mma_kernel,
                         cudaFuncAttributeMaxDynamicSharedMemorySize, C1_SMEM);
    cudaFuncSetAttribute(conv2_mma_kernel,
                         cudaFuncAttributeMaxDynamicSharedMemorySize, G_SMEM);
    cudaFuncSetAttribute(out_mma_kernel,
                         cudaFuncAttributeMaxDynamicSharedMemorySize, G_SMEM);

    split_w1_kernel<<<12544, 256>>>(w1);
    split_x_kernel<<<dim3(32, 8, 64), dim3(32, 8)>>>(x);
    prof_pad_kernel<<<1, 32>>>();                       // keeps conv1 at ncu launch idx 3
    conv1_mma_kernel<<<dim3(512, 2), 256, C1_SMEM>>>(b1);
    bn1_final_kernel<<<256, 256>>>(g1, bb1);
    fold2_kernel<<<1024, 256>>>(w2, b2);
    conv2_mma_kernel<<<dim3(256, 8), 256, G_SMEM>>>();
    bn2_final_kernel<<<1024, 256>>>(g2, bb2);
    softmax_rows_kernel<<<8192, 256>>>();
    out_mma_kernel<<<512, 256, G_SMEM>>>(out);
}

// round 17
// speedup vs baseline: 1.0038x; 1.0038x over previous
#include <cuda_runtime.h>
#include <cuda_bf16.h>
#include <cstdint>
#include <cstddef>

#define BDIM 64
#define CIN  256
#define CO1  256
#define HWP  1024
#define LF2  1024

// ---------------- scratch (device globals; no allocation) ----------------
__device__ float g_kT[(size_t)BDIM * HWP * LF2];     // conv2 output, [b][n][oc] fp32
__device__ float g_w2beta[LF2];
__device__ float g_a1[CO1], g_d1[CO1];
__device__ float g_a2[LF2], g_d2[LF2];
__device__ float g_p1s[1024 * 256],  g_p1ss[1024 * 256];   // conv1-fused BN1 partials
__device__ float g_p2s[512 * 1024],  g_p2ss[512 * 1024];   // conv2-fused BN2 partials
// conv1 weights: packed 2-tap stage tiles, K=16 chunks, taps padded 49->50.
// stage_id = (kc16*25 + tp)*2 + coHalf ; stage tile = 2 taps x (128 co x 80B).
// Pad tap 49 tiles are never written -> stay zero (device globals zero-init).
__device__ __align__(128) char g_wpk[16 * 25 * 2 * 20480];
// conv1 x operand: [b][uv][ci] bf16 hi/mid
__device__ __align__(16) __nv_bfloat16 g_xhi [(size_t)BDIM * HWP * CIN];
__device__ __align__(16) __nv_bfloat16 g_xmid[(size_t)BDIM * HWP * CIN];
// out-GEMM B operand: x split, original layout [b][ci][uv]
__device__ __align__(16) __nv_bfloat16 g_xchi [(size_t)BDIM * CIN * HWP];
__device__ __align__(16) __nv_bfloat16 g_xcmid[(size_t)BDIM * CIN * HWP];
// conv1 output transposed split: [b][px][c]
__device__ __align__(16) __nv_bfloat16 g_hThi [(size_t)BDIM * HWP * CIN];
__device__ __align__(16) __nv_bfloat16 g_hTmid[(size_t)BDIM * HWP * CIN];
// conv2 folded weights split: [oc][c]
__device__ __align__(16) __nv_bfloat16 g_w2fhi [LF2 * CIN];
__device__ __align__(16) __nv_bfloat16 g_w2fmid[LF2 * CIN];
// softmax output transposed split: [b][n][uv]
__device__ __align__(16) __nv_bfloat16 g_sThi [(size_t)BDIM * HWP * LF2];
__device__ __align__(16) __nv_bfloat16 g_sTmid[(size_t)BDIM * HWP * LF2];

// ---------------- family-common PTX helpers ----------------
__device__ __forceinline__ uint32_t smem_u32(const void* p) {
    uint32_t a;
    asm("{ .reg .u64 t; cvta.to.shared.u64 t, %1; cvt.u32.u64 %0, t; }" : "=r"(a) : "l"(p));
    return a;
}
__device__ __forceinline__ void cp_async16(uint32_t dst, const void* src, uint32_t srcsize) {
    asm volatile("cp.async.cg.shared.global [%0], [%1], 16, %2;"
                 :: "r"(dst), "l"(src), "r"(srcsize));
}
__device__ __forceinline__ void cp_commit() {
    asm volatile("cp.async.commit_group;");
}
template <int N> __device__ __forceinline__ void cp_wait() {
    asm volatile("cp.async.wait_group %0;" :: "n"(N));
}
// 1D bulk copy gmem->smem, mbarrier-completed (async engine, bypasses LSU)
__device__ __forceinline__ void cp_bulk_g2s(uint32_t dst, const void* src,
                                            uint32_t bytes, uint32_t mbar) {
    asm volatile(
        "cp.async.bulk.shared::cluster.global.mbarrier::complete_tx::bytes [%0], [%1], %2, [%3];"
        :: "r"(dst), "l"(src), "r"(bytes), "r"(mbar) : "memory");
}
#define MBARRIER_INIT(addr, count) \
    asm volatile("mbarrier.init.shared.b64 [%0], %1;" \
        :: "r"((uint32_t)(addr)), "r"((uint32_t)(count)) : "memory")
#define MBARRIER_EXPECT_TX(addr, bytes) \
    asm volatile("mbarrier.arrive.expect_tx.shared.b64 _, [%0], %1;" \
        :: "r"((uint32_t)(addr)), "r"((uint32_t)(bytes)) : "memory")
#define MBARRIER_WAIT_PARITY(mbar_smem_addr, phase_parity) do { \
    uint32_t _mbar = (uint32_t)(mbar_smem_addr); \
    uint32_t _parity = (uint32_t)(phase_parity); \
    uint32_t _done; \
    asm volatile("{ .reg .pred p; mbarrier.try_wait.parity.acquire.cta.shared::cta.b64 p, [%1], %2; selp.b32 %0, 1, 0, p; }" \
        : "=r"(_done) : "r"(_mbar), "r"(_parity) : "memory"); \
    if (!_done) { \
        asm volatile("{ .reg .pred P1; WAIT_LOOP_%=: mbarrier.try_wait.parity.acquire.cta.shared::cta.b64 P1, [%0], %1, 0x989680; @P1 bra.uni WAIT_DONE_%=; bra.uni WAIT_LOOP_%=; WAIT_DONE_%=: }" \
            :: "r"(_mbar), "r"(_parity) : "memory"); \
    } \
} while (0)

__device__ __forceinline__ void ldsm4(uint32_t* r, uint32_t addr) {
    asm volatile("ldmatrix.sync.aligned.m8n8.x4.shared.b16 {%0,%1,%2,%3}, [%4];"
                 : "=r"(r[0]), "=r"(r[1]), "=r"(r[2]), "=r"(r[3]) : "r"(addr));
}
__device__ __forceinline__ void mma_bf16(float* c, const uint32_t* a, const uint32_t* b) {
    asm volatile(
        "mma.sync.aligned.m16n8k16.row.col.f32.bf16.bf16.f32 "
        "{%0,%1,%2,%3}, {%4,%5,%6,%7}, {%8,%9}, {%0,%1,%2,%3};"
        : "+f"(c[0]), "+f"(c[1]), "+f"(c[2]), "+f"(c[3])
        : "r"(a[0]), "r"(a[1]), "r"(a[2]), "r"(a[3]), "r"(b[0]), "r"(b[1]));
}

// ---------------- prep (merged): w1 repack AND x splits in one launch ----------------
// blocks [0, 12544): w1 -> packed 2-tap K16 stage tiles
// blocks [12544, 12544+16384): x -> [b][uv][ci] and [b][ci][uv] bf16 hi/mid
__global__ void prep_kernel(const float* __restrict__ w1, const float* __restrict__ x) {
    if (blockIdx.x < 12544) {
        int i = blockIdx.x * 256 + threadIdx.x;
        int ci = i & 255, co = (i >> 8) & 255, tap = i >> 16;
        float v = w1[(co * 256 + ci) * 49 + tap];
        __nv_bfloat16 hi = __float2bfloat16(v);
        __nv_bfloat16 mid = __float2bfloat16(v - __bfloat162float(hi));
        int kc = ci >> 4, ciw = ci & 15;
        int stage = (kc * 25 + (tap >> 1)) * 2 + (co >> 7);
        char* tb = g_wpk + (size_t)stage * 20480 + (tap & 1) * 10240 + (co & 127) * 80;
        *(__nv_bfloat16*)(tb + ciw * 2)      = hi;   // bytes [0,32)
        *(__nv_bfloat16*)(tb + 32 + ciw * 2) = mid;  // bytes [32,64); [64,80) pad
        return;
    }
    // x-split path: decode (uv0, ci0, b) from linear block id; block = (32,8) work in 1D
    __shared__ float t[32][33];
    int blk = blockIdx.x - 12544;          // 0 .. 16383
    int uv0 = (blk & 31) << 5;             // 32 tiles
    int ci0 = ((blk >> 5) & 7) << 5;       // 8 tiles
    int b   = blk >> 8;                    // 64 batches
    int tx = threadIdx.x & 31, ty = threadIdx.x >> 5;   // (32, 8)
#pragma unroll
    for (int r = 0; r < 4; r++) {
        int ci = ci0 + ty + r * 8;
        float v = x[((size_t)(b * 256 + ci) << 10) + uv0 + tx];
        t[ty + r * 8][tx] = v;
        __nv_bfloat16 hi = __float2bfloat16(v);
        size_t o = ((size_t)(b * 256 + ci) << 10) + uv0 + tx;
        g_xchi[o]  = hi;
        g_xcmid[o] = __float2bfloat16(v - __bfloat162float(hi));
    }
    __syncthreads();
#pragma unroll
    for (int r = 0; r < 4; r++) {
        int uv = uv0 + ty + r * 8;
        float v = t[tx][ty + r * 8];
        __nv_bfloat16 hi = __float2bfloat16(v);
        size_t o = ((size_t)b << 18) + ((size_t)uv << 8) + ci0 + tx;
        g_xhi[o]  = hi;
        g_xmid[o] = __float2bfloat16(v - __bfloat162float(hi));
    }
}

// ---------------- conv1: K16 halo reuse + 2-tap bulk A stages + 2 CTAs/SM ----------------
// 16 kc16 chunks; per chunk load 704-px halo (hi/mid, 48B rows) once, run 25 2-tap stages.
#define C1_AT     20480
#define C1_RROW   48
#define C1_REG    (704 * C1_RROW)            // 33792
#define C1_A0     1024
#define C1_RH     (1024 + 2 * C1_AT)         // 41984
#define C1_RM     (C1_RH + C1_REG)           // 75776
#define C1_SMEM   (C1_RM + C1_REG)           // 109568

__device__ __forceinline__ void conv1_issue_A(uint32_t sb, int coh, int s) {
    int stage = s * 2 + coh;
    uint32_t mbar = sb + (uint32_t)(s & 1) * 8;
    MBARRIER_EXPECT_TX(mbar, 20480u);
    cp_bulk_g2s(sb + C1_A0 + (uint32_t)(s & 1) * C1_AT,
                g_wpk + (size_t)stage * 20480, 20480u, mbar);
}

__global__ __launch_bounds__(256, 2) void conv1_mma_kernel(const float* __restrict__ b1) {
    extern __shared__ char smem[];
    const uint32_t sb = smem_u32(smem);
    const int tid  = threadIdx.x;
    const int lane = tid & 31;
    const int wid  = tid >> 5;
    const int wm   = wid >> 1;          // 0..3: 32 co each
    const int wn   = wid & 1;           // 0..1: 64 px each
    const int bt   = blockIdx.x;
    const int b    = bt >> 3;
    const int i0   = (bt & 7) << 2;
    const int coh  = blockIdx.y;        // co half 0/1
    const int co0  = coh << 7;

    if (tid == 0) { MBARRIER_INIT(sb, 1); MBARRIER_INIT(sb + 8, 1); }
    __syncthreads();

    float acc[2][8][4];
#pragma unroll
    for (int mf = 0; mf < 2; mf++)
#pragma unroll
        for (int nf = 0; nf < 8; nf++)
#pragma unroll
            for (int e = 0; e < 4; e++) acc[mf][nf][e] = 0.f;

    const uint32_t aRow = (uint32_t)((wm * 32 + (lane & 15)) * 80 + (lane >> 4) * 16);

    if (tid == 0) conv1_issue_A(sb, coh, 0);

    int s = 0;
    for (int kc = 0; kc < 16; kc++) {
        // ---- load halo region for this kc16: (u,v), u in [i0-6,i0+10), v in [-6,38) ----
        {
            const __nv_bfloat16* xh = g_xhi  + ((size_t)b << 18) + (kc << 4);
            const __nv_bfloat16* xm = g_xmid + ((size_t)b << 18) + (kc << 4);
#pragma unroll
            for (int l = 0; l < 11; l++) {
                int idx = l * 256 + tid;              // 0..2815
                int px = idx >> 2;                    // 0..703
                int sel = idx & 3;
                int c16 = sel & 1;                    // 16B chunk within 32B
                int arr = sel >> 1;                   // 0=hi, 1=mid
                int ur = px / 44, vr = px - ur * 44;
                int u = i0 - 6 + ur;
                int v = vr - 6;
                bool in = ((unsigned)u < 32u) && ((unsigned)v < 32u);
                int pix = in ? (u * 32 + v) : 0;
                uint32_t sz = in ? 16u : 0u;
                uint32_t off = (uint32_t)(px * C1_RROW + c16 * 16);
                const __nv_bfloat16* src = (arr ? xm : xh) + ((size_t)pix << 8) + c16 * 8;
                cp_async16(sb + (arr ? C1_RM : C1_RH) + off, src, sz);
            }
            cp_commit();
            cp_wait<0>();
            __syncthreads();
        }
        // ---- 25 stages x 2 taps against the resident region ----
        for (int tp = 0; tp < 25; tp++, s++) {
            const int buf = s & 1;
            MBARRIER_WAIT_PARITY(sb + buf * 8, (s >> 1) & 1);   // A stage s landed
            __syncthreads();   // all warps done with stage s-1 -> its A buffer reusable
            if (tid == 0 && s + 1 < 400) conv1_issue_A(sb, coh, s + 1);

            const uint32_t aT = sb + C1_A0 + (uint32_t)buf * C1_AT;
#pragma unroll
            for (int j = 0; j < 2; j++) {
                int tap = tp * 2 + j;
                int btap = (tap > 48) ? 48 : tap;   // pad tap: zero A tile, clamped B addr
                const int dp = (btap / 7) * 2 - 6;
                const int dq = (btap % 7) * 2 - 6;
                uint32_t ah[2][4], am[2][4];
#pragma unroll
                for (int mf = 0; mf < 2; mf++) {
                    uint32_t addr = aT + (uint32_t)(j * 10240) + aRow + (uint32_t)(mf * 16 * 80);
                    ldsm4(ah[mf], addr);
                    ldsm4(am[mf], addr + 32);
                }
#pragma unroll
                for (int nf2 = 0; nf2 < 4; nf2++) {
                    int n0 = wn * 64 + nf2 * 16;
                    uint32_t pb = (uint32_t)((((n0 >> 5) + dp + 6) * 44 + (n0 & 31) + dq + 6
                                              + (lane & 15)) * C1_RROW + (lane >> 4) * 16);
                    uint32_t r[4];
                    uint32_t bh[2][2], bm[2][2];
                    ldsm4(r, sb + C1_RH + pb);
                    bh[0][0] = r[0]; bh[0][1] = r[2];
                    bh[1][0] = r[1]; bh[1][1] = r[3];
                    ldsm4(r, sb + C1_RM + pb);
                    bm[0][0] = r[0]; bm[0][1] = r[2];
                    bm[1][0] = r[1]; bm[1][1] = r[3];
#pragma unroll
                    for (int mf = 0; mf < 2; mf++)
#pragma unroll
                        for (int jj = 0; jj < 2; jj++) {
                            mma_bf16(acc[mf][nf2 * 2 + jj], ah[mf], bh[jj]);
                            mma_bf16(acc[mf][nf2 * 2 + jj], ah[mf], bm[jj]);
                            mma_bf16(acc[mf][nf2 * 2 + jj], am[mf], bh[jj]);
                        }
                }
            }
        }
        __syncthreads();   // all warps done with region before kc+1 reload
    }

    // epilogue: +bias, split bf16 hi/mid, smem-transpose to [px][co], write g_hT
    __nv_bfloat16* hs = (__nv_bfloat16*)smem;            // [128 px][136]
    __nv_bfloat16* ms = hs + 128 * 136;
#pragma unroll
    for (int mf = 0; mf < 2; mf++) {
        int R = wm * 32 + mf * 16 + (lane >> 2);
        float bias0 = b1[co0 + R];
        float bias8 = b1[co0 + R + 8];
#pragma unroll
        for (int nf = 0; nf < 8; nf++) {
            int C = wn * 64 + nf * 8 + (lane & 3) * 2;
#pragma unroll
            for (int e = 0; e < 4; e++) {
                float v = acc[mf][nf][e] + ((e & 2) ? bias8 : bias0);
                int px = C + (e & 1);
                int co = R + ((e & 2) ? 8 : 0);
                __nv_bfloat16 hi = __float2bfloat16(v);
                hs[px * 136 + co] = hi;
                ms[px * 136 + co] = __float2bfloat16(v - __bfloat162float(hi));
            }
        }
    }
    __syncthreads();
    {
        int px = tid >> 1;
        int half = tid & 1;
        size_t dst = (((size_t)b * HWP + i0 * 32 + px) << 8) + co0 + half * 64;
        const uint4* srcH = (const uint4*)(hs + px * 136 + half * 64);
        const uint4* srcM = (const uint4*)(ms + px * 136 + half * 64);
        uint4* dH = (uint4*)(g_hThi  + dst);
        uint4* dM = (uint4*)(g_hTmid + dst);
#pragma unroll
        for (int q = 0; q < 8; q++) { dH[q] = srcH[q]; dM[q] = srcM[q]; }
    }
    // fused BN1 partial stats: per-co sum/ssq over this CTA's 128 px
    {
        int co = tid & 127, half = tid >> 7;
        float s2 = 0.f, ss = 0.f;
#pragma unroll 8
        for (int p = 0; p < 64; p++) {
            int px = half * 64 + p;
            float v = __bfloat162float(hs[px * 136 + co]) + __bfloat162float(ms[px * 136 + co]);
            s2 += v; ss += v * v;
        }
        int prow = bt * 2 + half;
        g_p1s [prow * 256 + co0 + co] = s2;
        g_p1ss[prow * 256 + co0 + co] = ss;
    }
}

// ---------------- BN1 final: reduce 1024 partial rows -> a,d ----------------
__global__ void bn1_final_kernel(const float* __restrict__ gamma,
                                 const float* __restrict__ beta) {
    int c = blockIdx.x, t = threadIdx.x;
    __shared__ float sh[256], sh2[256];
    sh[t]  = g_p1s [t * 256 + c] + g_p1s [(t + 256) * 256 + c]
           + g_p1s [(t + 512) * 256 + c] + g_p1s [(t + 768) * 256 + c];
    sh2[t] = g_p1ss[t * 256 + c] + g_p1ss[(t + 256) * 256 + c]
           + g_p1ss[(t + 512) * 256 + c] + g_p1ss[(t + 768) * 256 + c];
    __syncthreads();
    for (int st = 128; st > 0; st >>= 1) {
        if (t < st) { sh[t] += sh[t + st]; sh2[t] += sh2[t + st]; }
        __syncthreads();
    }
    if (t == 0) {
        float mean = sh[0] * (1.f / 65536.f);
        float var  = sh2[0] * (1.f / 65536.f) - mean * mean;
        float a = gamma[c] * rsqrtf(var + 1e-5f);
        g_a1[c] = a;
        g_d1[c] = beta[c] - mean * a;
    }
}

// ---------------- fold BN1 into conv2 weights, split bf16 ----------------
__global__ void fold2_kernel(const float* __restrict__ w2, const float* __restrict__ b2) {
    int oc = blockIdx.x;
    int c  = threadIdx.x;
    float wv = w2[oc * CIN + c];
    float wf = wv * g_a1[c];
    __nv_bfloat16 hi = __float2bfloat16(wf);
    g_w2fhi[oc * 256 + c]  = hi;
    g_w2fmid[oc * 256 + c] = __float2bfloat16(wf - __bfloat162float(hi));
    __shared__ float sh[256];
    sh[c] = wv * g_d1[c];
    __syncthreads();
    for (int st = 128; st > 0; st >>= 1) {
        if (c < st) sh[c] += sh[c + st];
        __syncthreads();
    }
    if (c == 0) g_w2beta[oc] = b2[oc] + sh[0];
}

// ---------------- shared GEMM geometry for conv2 / out (128 M x 256 N tiles) ----------------
#define T_A     18432              // 128 * 144
#define T_B     36864              // 256 * 144
#define G_STAGE (2 * T_A + 2 * T_B)  // 110592
#define G_SMEM  (2 * G_STAGE)        // 221184

// ---------------- conv2: A = w2f [oc][c], B = hT [b][px][c]; C -> g_kT [b][n][oc] ----------------
__device__ __forceinline__ void c2_issue(uint32_t base, int b, int px0, int oc0, int kc, int tid) {
    const __nv_bfloat16* Ah = g_w2fhi  + (size_t)oc0 * 256 + kc * 64;
    const __nv_bfloat16* Am = g_w2fmid + (size_t)oc0 * 256 + kc * 64;
    const __nv_bfloat16* Bh = g_hThi  + (((size_t)b * HWP + px0) << 8) + kc * 64;
    const __nv_bfloat16* Bm = g_hTmid + (((size_t)b * HWP + px0) << 8) + kc * 64;
#pragma unroll
    for (int l = 0; l < 4; l++) {
        int idx = l * 256 + tid;
        int row = idx >> 3, c16 = idx & 7;
        uint32_t off = (uint32_t)(row * 144 + c16 * 16);
        cp_async16(base + off,       Ah + row * 256 + c16 * 8, 16);
        cp_async16(base + T_A + off, Am + row * 256 + c16 * 8, 16);
    }
#pragma unroll
    for (int l = 0; l < 8; l++) {
        int idx = l * 256 + tid;
        int row = idx >> 3, c16 = idx & 7;
        uint32_t off = (uint32_t)(row * 144 + c16 * 16);
        cp_async16(base + 2 * T_A + off,       Bh + (size_t)row * 256 + c16 * 8, 16);
        cp_async16(base + 2 * T_A + T_B + off, Bm + (size_t)row * 256 + c16 * 8, 16);
    }
}

__global__ __launch_bounds__(256, 1) void conv2_mma_kernel() {
    extern __shared__ char smem[];
    const uint32_t sb = smem_u32(smem);
    const int tid = threadIdx.x, lane = tid & 31, wid = tid >> 5;
    const int wm = wid >> 1, wn = wid & 1;
    const int bx = blockIdx.x;
    const int b = bx >> 2, px0 = (bx & 3) << 8;
    const int oc0 = blockIdx.y << 7;

    float acc[2][16][4];
#pragma unroll
    for (int mf = 0; mf < 2; mf++)
#pragma unroll
        for (int nf = 0; nf < 16; nf++)
#pragma unroll
            for (int e = 0; e < 4; e++) acc[mf][nf][e] = 0.f;

    const uint32_t a_rowoff = (uint32_t)((wm * 32 + (lane & 15)) * 144 + (lane >> 4) * 16);
    const uint32_t b_rowoff = (uint32_t)((wn * 128 + (lane & 15)) * 144 + (lane >> 4) * 16);

    c2_issue(sb, b, px0, oc0, 0, tid);
    cp_commit();
    for (int it = 0; it < 4; it++) {
        if (it < 3) {
            c2_issue(sb + (uint32_t)(((it + 1) & 1) * G_STAGE), b, px0, oc0, it + 1, tid);
            cp_commit();
            cp_wait<1>();
        } else {
            cp_wait<0>();
        }
        __syncthreads();
        const uint32_t cur = sb + (uint32_t)((it & 1) * G_STAGE);
#pragma unroll
        for (int ks = 0; ks < 4; ks++) {
            const uint32_t koff = (uint32_t)(ks * 32);
            uint32_t ah[2][4], am[2][4];
#pragma unroll
            for (int mf = 0; mf < 2; mf++) {
                uint32_t addr = cur + a_rowoff + (uint32_t)(mf * 16 * 144) + koff;
                ldsm4(ah[mf], addr);
                ldsm4(am[mf], addr + T_A);
            }
#pragma unroll
            for (int h = 0; h < 2; h++) {
                uint32_t bh[8][2], bm[8][2];
#pragma unroll
                for (int j = 0; j < 4; j++) {
                    uint32_t r[4];
                    uint32_t addr = cur + 2 * T_A + b_rowoff + (uint32_t)((h * 4 + j) * 16 * 144) + koff;
                    ldsm4(r, addr);
                    bh[j * 2][0] = r[0]; bh[j * 2][1] = r[2];
                    bh[j * 2 + 1][0] = r[1]; bh[j * 2 + 1][1] = r[3];
                    ldsm4(r, addr + T_B);
                    bm[j * 2][0] = r[0]; bm[j * 2][1] = r[2];
                    bm[j * 2 + 1][0] = r[1]; bm[j * 2 + 1][1] = r[3];
                }
#pragma unroll
                for (int mf = 0; mf < 2; mf++)
#pragma unroll
                    for (int nf = 0; nf < 8; nf++) {
                        mma_bf16(acc[mf][h * 8 + nf], ah[mf], bh[nf]);
                        mma_bf16(acc[mf][h * 8 + nf], ah[mf], bm[nf]);
                        mma_bf16(acc[mf][h * 8 + nf], am[mf], bh[nf]);
                    }
            }
        }
        __syncthreads();
    }

    // epilogue: +beta2, smem transpose to [px 256][oc 128], write g_kT rows
    float* ts = (float*)smem;    // [256][132]
#pragma unroll
    for (int mf = 0; mf < 2; mf++) {
        int R = wm * 32 + mf * 16 + (lane >> 2);
        float be0 = g_w2beta[oc0 + R];
        float be8 = g_w2beta[oc0 + R + 8];
#pragma unroll
        for (int nf = 0; nf < 16; nf++) {
            int C = wn * 128 + nf * 8 + (lane & 3) * 2;
#pragma unroll
            for (int e = 0; e < 4; e++) {
                int px = C + (e & 1);
                int co = R + ((e & 2) ? 8 : 0);
                ts[px * 132 + co] = acc[mf][nf][e] + ((e & 2) ? be8 : be0);
            }
        }
    }
    __syncthreads();
    {
        int px = tid;
        const uint4* src = (const uint4*)(ts + px * 132);
        uint4* dst = (uint4*)(g_kT + (((size_t)b * HWP + px0 + px) << 10) + oc0);
#pragma unroll
        for (int q = 0; q < 32; q++) dst[q] = src[q];
    }
    // fused BN2 partial stats: per-oc sum/ssq over this CTA's 256 px
    {
        int oc = tid & 127, half = tid >> 7;
        float s = 0.f, ss = 0.f;
#pragma unroll 8
        for (int p = 0; p < 128; p++) {
            float v = ts[(half * 128 + p) * 132 + oc];
            s += v; ss += v * v;
        }
        int prow = bx * 2 + half;
        g_p2s [prow * 1024 + oc0 + oc] = s;
        g_p2ss[prow * 1024 + oc0 + oc] = ss;
    }
}

// ---------------- BN2 final: reduce 512 partial rows -> a,d ----------------
__global__ void bn2_final_kernel(const float* __restrict__ gamma,
                                 const float* __restrict__ beta) {
    int c = blockIdx.x, t = threadIdx.x;
    __shared__ float sh[256], sh2[256];
    sh[t]  = g_p2s [t * 1024 + c] + g_p2s [(t + 256) * 1024 + c];
    sh2[t] = g_p2ss[t * 1024 + c] + g_p2ss[(t + 256) * 1024 + c];
    __syncthreads();
    for (int st = 128; st > 0; st >>= 1) {
        if (t < st) { sh[t] += sh[t + st]; sh2[t] += sh2[t + st]; }
        __syncthreads();
    }
    if (t == 0) {
        float mean = sh[0] * (1.f / 65536.f);
        float var  = sh2[0] * (1.f / 65536.f) - mean * mean;
        float a = gamma[c] * rsqrtf(var + 1e-5f);
        g_a2[c] = a;
        g_d2[c] = beta[c] - mean * a;
    }
}

// ---------------- BN2 + softmax: warp-per-row, no block barriers in row path ----------------
__global__ __launch_bounds__(256) void softmax_rows_kernel() {
    __shared__ float sa[LF2], sd[LF2];
    int tid = threadIdx.x;
    for (int i = tid; i < LF2; i += 256) { sa[i] = g_a2[i]; sd[i] = g_d2[i]; }
    __syncthreads();
    int wid = tid >> 5, lane = tid & 31;
    size_t r = (size_t)blockIdx.x * 8 + wid;
    const float* src = g_kT + (r << 10);
    float e[32];
    float s = 0.f;
#pragma unroll
    for (int k = 0; k < 32; k++) {
        int oc = lane + k * 32;
        float v = src[oc] * sa[oc] + sd[oc];
        e[k] = __expf(v);
        s += e[k];
    }
#pragma unroll
    for (int o = 16; o > 0; o >>= 1) s += __shfl_xor_sync(0xffffffffu, s, o);
    float inv = 1.f / s;
    __nv_bfloat16* dh = g_sThi  + (r << 10);
    __nv_bfloat16* dm = g_sTmid + (r << 10);
#pragma unroll
    for (int k = 0; k < 32; k++) {
        int oc = lane + k * 32;
        float p = e[k] * inv;
        __nv_bfloat16 hi = __float2bfloat16(p);
        dh[oc] = hi;
        dm[oc] = __float2bfloat16(p - __bfloat162float(hi));
    }
}

// ---------------- out GEMM: A = S^T [b][n][uv], B = x [b][c][uv]; C -> out[b][n][c] ----------------
__device__ __forceinline__ void out_issue(uint32_t base, int b, int n0, int kc, int tid) {
    const __nv_bfloat16* Ah = g_sThi  + (((size_t)b * HWP + n0) << 10) + kc * 64;
    const __nv_bfloat16* Am = g_sTmid + (((size_t)b * HWP + n0) << 10) + kc * 64;
    const __nv_bfloat16* Bh = g_xchi  + (((size_t)b * CIN) << 10) + kc * 64;
    const __nv_bfloat16* Bm = g_xcmid + (((size_t)b * CIN) << 10) + kc * 64;
#pragma unroll
    for (int l = 0; l < 4; l++) {
        int idx = l * 256 + tid;
        int row = idx >> 3, c16 = idx & 7;
        uint32_t off = (uint32_t)(row * 144 + c16 * 16);
        cp_async16(base + off,       Ah + ((size_t)row << 10) + c16 * 8, 16);
        cp_async16(base + T_A + off, Am + ((size_t)row << 10) + c16 * 8, 16);
    }
#pragma unroll
    for (int l = 0; l < 8; l++) {
        int idx = l * 256 + tid;
        int row = idx >> 3, c16 = idx & 7;
        uint32_t off = (uint32_t)(row * 144 + c16 * 16);
        cp_async16(base + 2 * T_A + off,       Bh + ((size_t)row << 10) + c16 * 8, 16);
        cp_async16(base + 2 * T_A + T_B + off, Bm + ((size_t)row << 10) + c16 * 8, 16);
    }
}

__global__ __launch_bounds__(256, 1) void out_mma_kernel(float* __restrict__ out) {
    extern __shared__ char smem[];
    const uint32_t sb = smem_u32(smem);
    const int tid = threadIdx.x, lane = tid & 31, wid = tid >> 5;
    const int wm = wid >> 1, wn = wid & 1;
    const int bx = blockIdx.x;
    const int b = bx >> 3, n0 = (bx & 7) << 7;

    float acc[2][16][4];
#pragma unroll
    for (int mf = 0; mf < 2; mf++)
#pragma unroll
        for (int nf = 0; nf < 16; nf++)
#pragma unroll
            for (int e = 0; e < 4; e++) acc[mf][nf][e] = 0.f;

    const uint32_t a_rowoff = (uint32_t)((wm * 32 + (lane & 15)) * 144 + (lane >> 4) * 16);
    const uint32_t b_rowoff = (uint32_t)((wn * 128 + (lane & 15)) * 144 + (lane >> 4) * 16);

    out_issue(sb, b, n0, 0, tid);
    cp_commit();
    for (int it = 0; it < 16; it++) {
        if (it < 15) {
            out_issue(sb + (uint32_t)(((it + 1) & 1) * G_STAGE), b, n0, it + 1, tid);
            cp_commit();
            cp_wait<1>();
        } else {
            cp_wait<0>();
        }
        __syncthreads();
        const uint32_t cur = sb + (uint32_t)((it & 1) * G_STAGE);
#pragma unroll
        for (int ks = 0; ks < 4; ks++) {
            const uint32_t koff = (uint32_t)(ks * 32);
            uint32_t ah[2][4], am[2][4];
#pragma unroll
            for (int mf = 0; mf < 2; mf++) {
                uint32_t addr = cur + a_rowoff + (uint32_t)(mf * 16 * 144) + koff;
                ldsm4(ah[mf], addr);
                ldsm4(am[mf], addr + T_A);
            }
#pragma unroll
            for (int h = 0; h < 2; h++) {
                uint32_t bh[8][2], bm[8][2];
#pragma unroll
                for (int j = 0; j < 4; j++) {
                    uint32_t r[4];
                    uint32_t addr = cur + 2 * T_A + b_rowoff + (uint32_t)((h * 4 + j) * 16 * 144) + koff;
                    ldsm4(r, addr);
                    bh[j * 2][0] = r[0]; bh[j * 2][1] = r[2];
                    bh[j * 2 + 1][0] = r[1]; bh[j * 2 + 1][1] = r[3];
                    ldsm4(r, addr + T_B);
                    bm[j * 2][0] = r[0]; bm[j * 2][1] = r[2];
                    bm[j * 2 + 1][0] = r[1]; bm[j * 2 + 1][1] = r[3];
                }
#pragma unroll
                for (int mf = 0; mf < 2; mf++)
#pragma unroll
                    for (int nf = 0; nf < 8; nf++) {
                        mma_bf16(acc[mf][h * 8 + nf], ah[mf], bh[nf]);
                        mma_bf16(acc[mf][h * 8 + nf], ah[mf], bm[nf]);
                        mma_bf16(acc[mf][h * 8 + nf], am[mf], bh[nf]);
                    }
            }
        }
        __syncthreads();
    }

    // epilogue: direct coalesced float2 stores to out[b][n][c]
#pragma unroll
    for (int mf = 0; mf < 2; mf++) {
        int n = n0 + wm * 32 + mf * 16 + (lane >> 2);
        float* row0 = out + ((size_t)b << 18) + (size_t)n * 256;
        float* row8 = row0 + 8 * 256;
#pragma unroll
        for (int nf = 0; nf < 16; nf++) {
            int C = wn * 128 + nf * 8 + (lane & 3) * 2;
            *(float2*)(row0 + C) = make_float2(acc[mf][nf][0], acc[mf][nf][1]);
            *(float2*)(row8 + C) = make_float2(acc[mf][nf][2], acc[mf][nf][3]);
        }
    }
}

// ---------------- launch ----------------
extern "C" void kernel_launch(void* const* d_in, const int* in_sizes, int n_in,
                              void* d_out, int out_size) {
    const float* x   = (const float*)d_in[0];
    const float* w1  = (const float*)d_in[1];
    const float* b1  = (const float*)d_in[2];
    const float* g1  = (const float*)d_in[3];
    const float* bb1 = (const float*)d_in[4];
    const float* w2  = (const float*)d_in[5];
    const float* b2  = (const float*)d_in[6];
    const float* g2  = (const float*)d_in[7];
    const float* bb2 = (const float*)d_in[8];
    float* out = (float*)d_out;

    cudaFuncSetAttribute(conv1_mma_kernel,
                         cudaFuncAttributeMaxDynamicSharedMemorySize, C1_SMEM);
    cudaFuncSetAttribute(conv2_mma_kernel,
                         cudaFuncAttributeMaxDynamicSharedMemorySize, G_SMEM);
    cudaFuncSetAttribute(out_mma_kernel,
                         cudaFuncAttributeMaxDynamicSharedMemorySize, G_SMEM);

    prep_kernel<<<12544 + 16384, 256>>>(w1, x);
    conv1_mma_kernel<<<dim3(512, 2), 256, C1_SMEM>>>(b1);
    bn1_final_kernel<<<256, 256>>>(g1, bb1);
    fold2_kernel<<<1024, 256>>>(w2, b2);
    conv2_mma_kernel<<<dim3(256, 8), 256, G_SMEM>>>();
    bn2_final_kernel<<<1024, 256>>>(g2, bb2);
    softmax_rows_kernel<<<8192, 256>>>();
    out_mma_kernel<<<512, 256, G_SMEM>>>(out);
}